// round 12
// baseline (speedup 1.0000x reference)
#include <cuda_runtime.h>
#include <cuda_fp16.h>
#include <cstdint>

#define L_SEQ   2048
#define NBATCH  2
#define NHEADS  16
#define HDIM    64
#define EMBED   1024
// Q pre-scale: 1/sqrt(1024) * log2(e)  -> S comes out in log2 domain
#define QSCALE  (0.03125f * 1.44269504f)
#define KT      64
#define NT      (L_SEQ / KT)
#define ONES2   0x3C003C00u   // fp16x2 {1.0, 1.0}

// ---------------- scratch (device globals; no allocation allowed) -------------
__device__ __half g_q[(size_t)NBATCH * NHEADS * L_SEQ * HDIM];
__device__ __half g_k[(size_t)NBATCH * NHEADS * L_SEQ * HDIM];
__device__ __half g_v[(size_t)NBATCH * NHEADS * L_SEQ * HDIM];
// fragment-ordered fp16 AND-masks: [n][qt128][kti][tid2][kk] as uint4
__device__ uint4 g_mf[(size_t)NBATCH * 16 * 32 * 256 * 4];

// ---------------- helpers -----------------------------------------------------
__device__ __forceinline__ unsigned pack2(float lo, float hi) {
    unsigned r;
    asm("cvt.rn.f16x2.f32 %0, %1, %2;" : "=r"(r) : "f"(hi), "f"(lo));
    return r;
}
__device__ __forceinline__ void mma16(float (&d)[4], const unsigned* a,
                                      unsigned b0, unsigned b1) {
    asm volatile(
        "mma.sync.aligned.m16n8k16.row.col.f32.f16.f16.f32 "
        "{%0,%1,%2,%3}, {%4,%5,%6,%7}, {%8,%9}, {%0,%1,%2,%3};"
        : "+f"(d[0]), "+f"(d[1]), "+f"(d[2]), "+f"(d[3])
        : "r"(a[0]), "r"(a[1]), "r"(a[2]), "r"(a[3]), "r"(b0), "r"(b1));
}
__device__ __forceinline__ void mma16h(unsigned& d0, unsigned& d1,
                                       const unsigned* a,
                                       unsigned b0, unsigned b1) {
    asm volatile(
        "mma.sync.aligned.m16n8k16.row.col.f16.f16.f16.f16 "
        "{%0,%1}, {%2,%3,%4,%5}, {%6,%7}, {%0,%1};"
        : "+r"(d0), "+r"(d1)
        : "r"(a[0]), "r"(a[1]), "r"(a[2]), "r"(a[3]), "r"(b0), "r"(b1));
}
__device__ __forceinline__ void mma16h_z(unsigned& d0, unsigned& d1,
                                         const unsigned* a,
                                         unsigned b0, unsigned b1) {
    asm volatile(
        "mma.sync.aligned.m16n8k16.row.col.f16.f16.f16.f16 "
        "{%0,%1}, {%2,%3,%4,%5}, {%6,%7}, {%8,%9};"
        : "=r"(d0), "=r"(d1)
        : "r"(a[0]), "r"(a[1]), "r"(a[2]), "r"(a[3]), "r"(b0), "r"(b1),
          "r"(0u), "r"(0u));
}
__device__ __forceinline__ void ex2h2(unsigned& x) {
    asm("ex2.approx.f16x2 %0, %0;" : "+r"(x));
}
__device__ __forceinline__ void ldm4(unsigned (&r)[4], uint32_t addr) {
    asm volatile("ldmatrix.sync.aligned.m8n8.x4.shared.b16 {%0,%1,%2,%3}, [%4];"
                 : "=r"(r[0]), "=r"(r[1]), "=r"(r[2]), "=r"(r[3]) : "r"(addr));
}
__device__ __forceinline__ void cpa16(uint32_t dst, const void* src) {
    asm volatile("cp.async.cg.shared.global [%0], [%1], 16;" :: "r"(dst), "l"(src));
}
#define CP_COMMIT()  asm volatile("cp.async.commit_group;")
#define CP_WAIT(N)   asm volatile("cp.async.wait_group %0;" :: "n"(N))

// ---- fragment-order half offsets (validated rounds 2-11) ---------------------
__device__ __forceinline__ int qa_off(int r, int c) {
    int lane = ((r & 7) << 2) | ((c & 7) >> 1);
    int reg  = ((r >> 3) & 1) | (((c >> 3) & 1) << 1);
    return ((r >> 4) << 10) + ((c >> 4) << 8) + (lane << 3) + (reg << 1) + (c & 1);
}
__device__ __forceinline__ int kb_off(int r, int c) {
    int lane = ((r & 7) << 2) | ((c & 7) >> 1);
    return ((c >> 4) << 10) + ((r >> 4) << 8) + (lane << 3) +
           (((r >> 3) & 1) << 2) + (((c >> 3) & 1) << 1) + (c & 1);
}
__device__ __forceinline__ int vb_off(int s, int d) {
    int lane = ((d & 7) << 2) | ((s & 7) >> 1);
    return ((s >> 4) << 10) + ((d >> 4) << 8) + (lane << 3) +
           (((d >> 3) & 1) << 2) + (((s >> 3) & 1) << 1) + (s & 1);
}

// ---------------- kernel 1: QKV projections + fragment-ordered mask -----------
#define XH_S 72
__global__ __launch_bounds__(256) void proj_kernel(
    const float* __restrict__ vals, const float* __restrict__ keys,
    const float* __restrict__ qrys,
    const float* __restrict__ Wv, const float* __restrict__ Wk,
    const float* __restrict__ Wq, const int* __restrict__ mask)
{
    __shared__ __half Xh[64 * XH_S];
    __shared__ __half Wh[64 * XH_S];
    __shared__ __half Ps[4096];

    const int lt = blockIdx.x, h = blockIdx.y, n = blockIdx.z;
    const int l0 = lt * 64;
    const int tid = threadIdx.x, warp = tid >> 5, lane = tid & 31;
    const int grp = lane >> 2, t = tid & 3;
    const int r0 = (warp & 3) * 16, n0 = (warp >> 2) * 32;

    // ---- fused mask fragment generation ----
    {
        const int unit = ((lt << 4) | h) * 256 + tid;
        const int qtm = unit >> 13;
        const int ktm = (unit >> 8) & 31;
        const int t2  = unit & 255;
        const int w2 = t2 >> 5, l2v = t2 & 31, g2 = l2v >> 2, tt = l2v & 3;
        const int raw = qtm * 128 + w2 * 16 + g2;
        const int* ma = mask + (size_t)n * L_SEQ * L_SEQ + (size_t)raw * L_SEQ
                             + ktm * 64 + 2 * tt;
        const int* mbp = ma + 8 * L_SEQ;
        uint4* dst = g_mf + (((size_t)(n * 16 + qtm) * 32 + ktm) * 256 + t2) * 4;
        #pragma unroll
        for (int kk = 0; kk < 4; ++kk) {
            int2 va  = *(const int2*)(ma  + kk * 16);
            int2 vb  = *(const int2*)(mbp + kk * 16);
            int2 va8 = *(const int2*)(ma  + kk * 16 + 8);
            int2 vb8 = *(const int2*)(mbp + kk * 16 + 8);
            uint4 f;
            f.x = (va.x  ? 0xFFFFu : 0u) | (va.y  ? 0xFFFF0000u : 0u);
            f.y = (vb.x  ? 0xFFFFu : 0u) | (vb.y  ? 0xFFFF0000u : 0u);
            f.z = (va8.x ? 0xFFFFu : 0u) | (va8.y ? 0xFFFF0000u : 0u);
            f.w = (vb8.x ? 0xFFFFu : 0u) | (vb8.y ? 0xFFFF0000u : 0u);
            dst[kk] = f;
        }
    }

    const float* Xsrc[3] = {vals, keys, qrys};
    const float* Wsrc[3] = {Wv, Wk, Wq};

    const uint32_t xh_u = (uint32_t)__cvta_generic_to_shared(Xh);
    const uint32_t wh_u = (uint32_t)__cvta_generic_to_shared(Wh);
    const int arow = r0 + (lane & 15), acol8 = (lane >> 4) << 3;
    const int brow = (lane & 7) | ((lane & 16) >> 1), bcol8 = lane & 8;

    for (int p = 0; p < 3; ++p) {
        for (int i = tid * 4; i < 4096; i += 1024) {
            int r = i >> 6, c = i & 63;
            float4 x = *(const float4*)(Xsrc[p] +
                ((size_t)(n * L_SEQ + l0 + r)) * EMBED + h * HDIM + c);
            *(unsigned*)(Xh + r * XH_S + c)     = pack2(x.x, x.y);
            *(unsigned*)(Xh + r * XH_S + c + 2) = pack2(x.z, x.w);
            float4 w = *(const float4*)(Wsrc[p] + i);
            *(unsigned*)(Wh + r * XH_S + c)     = pack2(w.x, w.y);
            *(unsigned*)(Wh + r * XH_S + c + 2) = pack2(w.z, w.w);
        }
        __syncthreads();

        float acc[4][4] = {};
        #pragma unroll
        for (int kk = 0; kk < 4; ++kk) {
            unsigned a[4];
            ldm4(a, xh_u + (arow * XH_S + kk * 16 + acol8) * 2);
            #pragma unroll
            for (int jp = 0; jp < 2; ++jp) {
                unsigned b[4];
                ldm4(b, wh_u + ((n0 + jp * 16 + brow) * XH_S + kk * 16 + bcol8) * 2);
                mma16(acc[jp * 2],     a, b[0], b[1]);
                mma16(acc[jp * 2 + 1], a, b[2], b[3]);
            }
        }
        __syncthreads();

        const int r1 = r0 + grp, r2 = r1 + 8;
        #pragma unroll
        for (int nb = 0; nb < 4; ++nb) {
            const int c0 = n0 + nb * 8 + 2 * t;
            if (p == 0) {
                Ps[vb_off(r1, c0)]     = __float2half_rn(acc[nb][0]);
                Ps[vb_off(r1, c0 + 1)] = __float2half_rn(acc[nb][1]);
                Ps[vb_off(r2, c0)]     = __float2half_rn(acc[nb][2]);
                Ps[vb_off(r2, c0 + 1)] = __float2half_rn(acc[nb][3]);
            } else if (p == 1) {
                *(unsigned*)(Ps + kb_off(r1, c0)) = pack2(acc[nb][0], acc[nb][1]);
                *(unsigned*)(Ps + kb_off(r2, c0)) = pack2(acc[nb][2], acc[nb][3]);
            } else {
                *(unsigned*)(Ps + qa_off(r1, c0)) =
                    pack2(acc[nb][0] * QSCALE, acc[nb][1] * QSCALE);
                *(unsigned*)(Ps + qa_off(r2, c0)) =
                    pack2(acc[nb][2] * QSCALE, acc[nb][3] * QSCALE);
            }
        }
        __syncthreads();

        const size_t hb = (size_t)(n * NHEADS + h) * L_SEQ * HDIM;
        __half* dst;
        if (p == 0)      dst = g_v + hb + (size_t)lt * 4096;
        else if (p == 1) dst = g_k + hb + (size_t)lt * 4096;
        else             dst = g_q + hb + (size_t)(l0 >> 7) * 8192 + ((l0 & 64) ? 4096 : 0);
        for (int i = tid; i < 512; i += 256)
            ((uint4*)dst)[i] = ((const uint4*)Ps)[i];
        __syncthreads();
    }
}

// ---------------- kernel 2: fp16 flash attention (4 warps, 2-wave softmax) ----
// smem bytes: KB[3] 8192 each | VB[3] 8192 each = 49152
#define OFF_KB  0
#define OFF_VB  24576
#define ATTN_SMEM 49152

__global__ __launch_bounds__(128, 3) void attn_kernel(float* __restrict__ out)
{
    extern __shared__ char smc[];
    const int qt = blockIdx.x, h = blockIdx.y, n = blockIdx.z;
    const int q0 = qt * 128;
    const int tid = threadIdx.x, warp = tid >> 5, lane = tid & 31;
    const int grp = lane >> 2, t = lane & 3;

    const __half* qg = g_q + ((size_t)(n * NHEADS + h) * 16 + qt) * 8192;
    const __half* kg = g_k + (size_t)(n * NHEADS + h) * L_SEQ * HDIM;
    const __half* vg = g_v + (size_t)(n * NHEADS + h) * L_SEQ * HDIM;
    // mask fragments for this warp's two 16-row blocks (2w, 2w+1)
    const uint4* mf0 = g_mf + ((size_t)(n * 16 + qt) * 32 * 256 + (2 * warp) * 32 + lane) * 4;
    const uint4* mf1 = mf0 + 32 * 4;

    const uint32_t sb = (uint32_t)__cvta_generic_to_shared(smc);

    // prologue: G0 = {K0, V0}; G1 = {K1, V1}   (128 threads x 4 uint4 = 512)
    #pragma unroll
    for (int j = 0; j < 4; ++j) {
        cpa16(sb + OFF_KB + (tid + j * 128) * 16, (const uint4*)kg + tid + j * 128);
        cpa16(sb + OFF_VB + (tid + j * 128) * 16, (const uint4*)vg + tid + j * 128);
    }
    CP_COMMIT();
    #pragma unroll
    for (int j = 0; j < 4; ++j) {
        cpa16(sb + OFF_KB + 8192 + (tid + j * 128) * 16, (const uint4*)(kg + 4096) + tid + j * 128);
        cpa16(sb + OFF_VB + 8192 + (tid + j * 128) * 16, (const uint4*)(vg + 4096) + tid + j * 128);
    }
    CP_COMMIT();

    // Q fragments for both row blocks (fragment-ordered gmem, one LDG pass)
    unsigned qa[2][4][4];
    #pragma unroll
    for (int b = 0; b < 2; ++b) {
        const uint4* qg4 = (const uint4*)qg + (2 * warp + b) * 128 + lane;
        #pragma unroll
        for (int kk = 0; kk < 4; ++kk) {
            uint4 v = qg4[kk * 32];
            qa[b][kk][0] = v.x; qa[b][kk][1] = v.y; qa[b][kk][2] = v.z; qa[b][kk][3] = v.w;
        }
    }

    float o[2][8][4];
    #pragma unroll
    for (int b = 0; b < 2; ++b)
        #pragma unroll
        for (int j = 0; j < 8; ++j)
            o[b][j][0] = o[b][j][1] = o[b][j][2] = o[b][j][3] = 0.f;
    float ld[2][4] = {};

    int cur = 0, nxt = 2;
    for (int kti = 0; kti < NT; ++kti) {
        CP_WAIT(1);
        __syncthreads();

        if (kti + 2 < NT) {
            const uint4* k2 = (const uint4*)(kg + (size_t)(kti + 2) * 4096);
            const uint4* v2 = (const uint4*)(vg + (size_t)(kti + 2) * 4096);
            const uint32_t kd = sb + OFF_KB + nxt * 8192;
            const uint32_t vd = sb + OFF_VB + nxt * 8192;
            #pragma unroll
            for (int j = 0; j < 4; ++j) {
                cpa16(kd + (tid + j * 128) * 16, k2 + tid + j * 128);
                cpa16(vd + (tid + j * 128) * 16, v2 + tid + j * 128);
            }
        }
        CP_COMMIT();

        const uint4* kb4 = (const uint4*)(smc + OFF_KB + cur * 8192) + lane;
        const uint4* vb4 = (const uint4*)(smc + OFF_VB + cur * 8192) + lane;

        // ---- two 32-column waves: S -> ex2+mask -> PV (+row-sum) ----
        #pragma unroll
        for (int wave = 0; wave < 2; ++wave) {
            // masks for this wave (2 uint4 per row block)
            uint4 mk0[2], mk1[2];
            #pragma unroll
            for (int j = 0; j < 2; ++j) {
                mk0[j] = mf0[(size_t)kti * 1024 + 2 * wave + j];
                mk1[j] = mf1[(size_t)kti * 1024 + 2 * wave + j];
            }

            // S wave: columns jp = 2*wave, 2*wave+1
            unsigned su[2][8];
            #pragma unroll
            for (int kk = 0; kk < 4; ++kk) {
                #pragma unroll
                for (int jw = 0; jw < 2; ++jw) {
                    uint4 bv = kb4[kk * 128 + (2 * wave + jw) * 32];
                    if (kk == 0) {
                        #pragma unroll
                        for (int b = 0; b < 2; ++b) {
                            mma16h_z(su[b][4 * jw],     su[b][4 * jw + 1], qa[b][0], bv.x, bv.y);
                            mma16h_z(su[b][4 * jw + 2], su[b][4 * jw + 3], qa[b][0], bv.z, bv.w);
                        }
                    } else {
                        #pragma unroll
                        for (int b = 0; b < 2; ++b) {
                            mma16h(su[b][4 * jw],     su[b][4 * jw + 1], qa[b][kk], bv.x, bv.y);
                            mma16h(su[b][4 * jw + 2], su[b][4 * jw + 3], qa[b][kk], bv.z, bv.w);
                        }
                    }
                }
            }

            // p = 2^S, AND-mask
            #pragma unroll
            for (int i = 0; i < 8; ++i) { ex2h2(su[0][i]); ex2h2(su[1][i]); }
            #pragma unroll
            for (int j = 0; j < 2; ++j) {
                su[0][4 * j]     &= mk0[j].x; su[0][4 * j + 1] &= mk0[j].y;
                su[0][4 * j + 2] &= mk0[j].z; su[0][4 * j + 3] &= mk0[j].w;
                su[1][4 * j]     &= mk1[j].x; su[1][4 * j + 1] &= mk1[j].y;
                su[1][4 * j + 2] &= mk1[j].z; su[1][4 * j + 3] &= mk1[j].w;
            }

            // PV wave: P chunks kk = 2*wave, 2*wave+1 ; row sums via ones-mma
            #pragma unroll
            for (int kw = 0; kw < 2; ++kw) {
                #pragma unroll
                for (int jp = 0; jp < 4; ++jp) {
                    uint4 bv = vb4[(2 * wave + kw) * 128 + jp * 32];
                    #pragma unroll
                    for (int b = 0; b < 2; ++b) {
                        mma16(o[b][jp * 2],     su[b] + 4 * kw, bv.x, bv.y);
                        mma16(o[b][jp * 2 + 1], su[b] + 4 * kw, bv.z, bv.w);
                    }
                }
                mma16(ld[0], su[0] + 4 * kw, ONES2, ONES2);
                mma16(ld[1], su[1] + 4 * kw, ONES2, ONES2);
            }
        }

        cur = (cur == 2) ? 0 : cur + 1;
        nxt = (nxt == 2) ? 0 : nxt + 1;
    }

    // ---- epilogue per row block ----
    #pragma unroll
    for (int b = 0; b < 2; ++b) {
        const int ra = (2 * warp + b) * 16 + grp;
        const float inv1 = 1.f / ld[b][0], inv2 = 1.f / ld[b][2];
        float* ob1 = out + ((size_t)(n * L_SEQ + q0 + ra)) * EMBED + h * HDIM;
        float* ob2 = out + ((size_t)(n * L_SEQ + q0 + ra + 8)) * EMBED + h * HDIM;
        #pragma unroll
        for (int j = 0; j < 8; ++j) {
            int c0 = j * 8 + 2 * t;
            *(float2*)(ob1 + c0) = make_float2(o[b][j][0] * inv1, o[b][j][1] * inv1);
            *(float2*)(ob2 + c0) = make_float2(o[b][j][2] * inv2, o[b][j][3] * inv2);
        }
    }
}

// ---------------- launch ------------------------------------------------------
extern "C" void kernel_launch(void* const* d_in, const int* in_sizes, int n_in,
                              void* d_out, int out_size)
{
    const float* values  = (const float*)d_in[0];
    const float* keys    = (const float*)d_in[1];
    const float* queries = (const float*)d_in[2];
    const int*   mask    = (const int*)d_in[3];
    const float* Wv      = (const float*)d_in[4];
    const float* Wk      = (const float*)d_in[5];
    const float* Wq      = (const float*)d_in[6];
    float* out = (float*)d_out;

    cudaFuncSetAttribute(attn_kernel, cudaFuncAttributeMaxDynamicSharedMemorySize, ATTN_SMEM);

    proj_kernel<<<dim3(L_SEQ / 64, NHEADS, NBATCH), 256>>>(
        values, keys, queries, Wv, Wk, Wq, mask);
    attn_kernel<<<dim3(L_SEQ / 128, NHEADS, NBATCH), 128, ATTN_SMEM>>>(out);
}

// round 14
// speedup vs baseline: 1.0470x; 1.0470x over previous
#include <cuda_runtime.h>
#include <cuda_fp16.h>
#include <cstdint>

#define L_SEQ   2048
#define NBATCH  2
#define NHEADS  16
#define HDIM    64
#define EMBED   1024
// Q pre-scale: 1/sqrt(1024) * log2(e)  -> S comes out in log2 domain
#define QSCALE  (0.03125f * 1.44269504f)
#define KT      64
#define NT      (L_SEQ / KT)
#define ONES2   0x3C003C00u   // fp16x2 {1.0, 1.0}

// ---------------- scratch (device globals; no allocation allowed) -------------
__device__ __half g_q[(size_t)NBATCH * NHEADS * L_SEQ * HDIM];
__device__ __half g_k[(size_t)NBATCH * NHEADS * L_SEQ * HDIM];
__device__ __half g_v[(size_t)NBATCH * NHEADS * L_SEQ * HDIM];
// fragment-ordered fp16 AND-masks: [n][qt128][kti][tid2][kk] as uint4
__device__ uint4 g_mf[(size_t)NBATCH * 16 * 32 * 256 * 4];

// ---------------- helpers -----------------------------------------------------
__device__ __forceinline__ unsigned pack2(float lo, float hi) {
    unsigned r;
    asm("cvt.rn.f16x2.f32 %0, %1, %2;" : "=r"(r) : "f"(hi), "f"(lo));
    return r;
}
__device__ __forceinline__ void mma16(float (&d)[4], const unsigned* a,
                                      unsigned b0, unsigned b1) {
    asm volatile(
        "mma.sync.aligned.m16n8k16.row.col.f32.f16.f16.f32 "
        "{%0,%1,%2,%3}, {%4,%5,%6,%7}, {%8,%9}, {%0,%1,%2,%3};"
        : "+f"(d[0]), "+f"(d[1]), "+f"(d[2]), "+f"(d[3])
        : "r"(a[0]), "r"(a[1]), "r"(a[2]), "r"(a[3]), "r"(b0), "r"(b1));
}
__device__ __forceinline__ void mma16h(unsigned& d0, unsigned& d1,
                                       const unsigned* a,
                                       unsigned b0, unsigned b1) {
    asm volatile(
        "mma.sync.aligned.m16n8k16.row.col.f16.f16.f16.f16 "
        "{%0,%1}, {%2,%3,%4,%5}, {%6,%7}, {%0,%1};"
        : "+r"(d0), "+r"(d1)
        : "r"(a[0]), "r"(a[1]), "r"(a[2]), "r"(a[3]), "r"(b0), "r"(b1));
}
__device__ __forceinline__ void mma16h_z(unsigned& d0, unsigned& d1,
                                         const unsigned* a,
                                         unsigned b0, unsigned b1) {
    asm volatile(
        "mma.sync.aligned.m16n8k16.row.col.f16.f16.f16.f16 "
        "{%0,%1}, {%2,%3,%4,%5}, {%6,%7}, {%8,%9};"
        : "=r"(d0), "=r"(d1)
        : "r"(a[0]), "r"(a[1]), "r"(a[2]), "r"(a[3]), "r"(b0), "r"(b1),
          "r"(0u), "r"(0u));
}
__device__ __forceinline__ void ex2h2(unsigned& x) {
    asm("ex2.approx.f16x2 %0, %0;" : "+r"(x));
}
__device__ __forceinline__ void ldm4(unsigned (&r)[4], uint32_t addr) {
    asm volatile("ldmatrix.sync.aligned.m8n8.x4.shared.b16 {%0,%1,%2,%3}, [%4];"
                 : "=r"(r[0]), "=r"(r[1]), "=r"(r[2]), "=r"(r[3]) : "r"(addr));
}
__device__ __forceinline__ void cpa16(uint32_t dst, const void* src) {
    asm volatile("cp.async.cg.shared.global [%0], [%1], 16;" :: "r"(dst), "l"(src));
}
#define CP_COMMIT()  asm volatile("cp.async.commit_group;")
#define CP_WAIT(N)   asm volatile("cp.async.wait_group %0;" :: "n"(N))

// ---- fragment-order half offsets (validated rounds 2-12) ---------------------
__device__ __forceinline__ int qa_off(int r, int c) {
    int lane = ((r & 7) << 2) | ((c & 7) >> 1);
    int reg  = ((r >> 3) & 1) | (((c >> 3) & 1) << 1);
    return ((r >> 4) << 10) + ((c >> 4) << 8) + (lane << 3) + (reg << 1) + (c & 1);
}
__device__ __forceinline__ int kb_off(int r, int c) {
    int lane = ((r & 7) << 2) | ((c & 7) >> 1);
    return ((c >> 4) << 10) + ((r >> 4) << 8) + (lane << 3) +
           (((r >> 3) & 1) << 2) + (((c >> 3) & 1) << 1) + (c & 1);
}
__device__ __forceinline__ int vb_off(int s, int d) {
    int lane = ((d & 7) << 2) | ((s & 7) >> 1);
    return ((s >> 4) << 10) + ((d >> 4) << 8) + (lane << 3) +
           (((d >> 3) & 1) << 2) + (((s >> 3) & 1) << 1) + (s & 1);
}

// ---------------- kernel 1: QKV projections + fragment-ordered mask -----------
#define XH_S 72
__global__ __launch_bounds__(256) void proj_kernel(
    const float* __restrict__ vals, const float* __restrict__ keys,
    const float* __restrict__ qrys,
    const float* __restrict__ Wv, const float* __restrict__ Wk,
    const float* __restrict__ Wq, const int* __restrict__ mask)
{
    __shared__ __half Xh[64 * XH_S];
    __shared__ __half Wh[64 * XH_S];
    __shared__ __half Ps[4096];

    const int lt = blockIdx.x, h = blockIdx.y, n = blockIdx.z;
    const int l0 = lt * 64;
    const int tid = threadIdx.x, warp = tid >> 5, lane = tid & 31;
    const int grp = lane >> 2, t = tid & 3;
    const int r0 = (warp & 3) * 16, n0 = (warp >> 2) * 32;

    // ---- fused mask fragment generation ----
    {
        const int unit = ((lt << 4) | h) * 256 + tid;
        const int qtm = unit >> 13;
        const int ktm = (unit >> 8) & 31;
        const int t2  = unit & 255;
        const int w2 = t2 >> 5, l2v = t2 & 31, g2 = l2v >> 2, tt = l2v & 3;
        const int raw = qtm * 128 + w2 * 16 + g2;
        const int* ma = mask + (size_t)n * L_SEQ * L_SEQ + (size_t)raw * L_SEQ
                             + ktm * 64 + 2 * tt;
        const int* mbp = ma + 8 * L_SEQ;
        uint4* dst = g_mf + (((size_t)(n * 16 + qtm) * 32 + ktm) * 256 + t2) * 4;
        #pragma unroll
        for (int kk = 0; kk < 4; ++kk) {
            int2 va  = *(const int2*)(ma  + kk * 16);
            int2 vb  = *(const int2*)(mbp + kk * 16);
            int2 va8 = *(const int2*)(ma  + kk * 16 + 8);
            int2 vb8 = *(const int2*)(mbp + kk * 16 + 8);
            uint4 f;
            f.x = (va.x  ? 0xFFFFu : 0u) | (va.y  ? 0xFFFF0000u : 0u);
            f.y = (vb.x  ? 0xFFFFu : 0u) | (vb.y  ? 0xFFFF0000u : 0u);
            f.z = (va8.x ? 0xFFFFu : 0u) | (va8.y ? 0xFFFF0000u : 0u);
            f.w = (vb8.x ? 0xFFFFu : 0u) | (vb8.y ? 0xFFFF0000u : 0u);
            dst[kk] = f;
        }
    }

    const float* Xsrc[3] = {vals, keys, qrys};
    const float* Wsrc[3] = {Wv, Wk, Wq};

    const uint32_t xh_u = (uint32_t)__cvta_generic_to_shared(Xh);
    const uint32_t wh_u = (uint32_t)__cvta_generic_to_shared(Wh);
    const int arow = r0 + (lane & 15), acol8 = (lane >> 4) << 3;
    const int brow = (lane & 7) | ((lane & 16) >> 1), bcol8 = lane & 8;

    for (int p = 0; p < 3; ++p) {
        for (int i = tid * 4; i < 4096; i += 1024) {
            int r = i >> 6, c = i & 63;
            float4 x = *(const float4*)(Xsrc[p] +
                ((size_t)(n * L_SEQ + l0 + r)) * EMBED + h * HDIM + c);
            *(unsigned*)(Xh + r * XH_S + c)     = pack2(x.x, x.y);
            *(unsigned*)(Xh + r * XH_S + c + 2) = pack2(x.z, x.w);
            float4 w = *(const float4*)(Wsrc[p] + i);
            *(unsigned*)(Wh + r * XH_S + c)     = pack2(w.x, w.y);
            *(unsigned*)(Wh + r * XH_S + c + 2) = pack2(w.z, w.w);
        }
        __syncthreads();

        float acc[4][4] = {};
        #pragma unroll
        for (int kk = 0; kk < 4; ++kk) {
            unsigned a[4];
            ldm4(a, xh_u + (arow * XH_S + kk * 16 + acol8) * 2);
            #pragma unroll
            for (int jp = 0; jp < 2; ++jp) {
                unsigned b[4];
                ldm4(b, wh_u + ((n0 + jp * 16 + brow) * XH_S + kk * 16 + bcol8) * 2);
                mma16(acc[jp * 2],     a, b[0], b[1]);
                mma16(acc[jp * 2 + 1], a, b[2], b[3]);
            }
        }
        __syncthreads();

        const int r1 = r0 + grp, r2 = r1 + 8;
        #pragma unroll
        for (int nb = 0; nb < 4; ++nb) {
            const int c0 = n0 + nb * 8 + 2 * t;
            if (p == 0) {
                Ps[vb_off(r1, c0)]     = __float2half_rn(acc[nb][0]);
                Ps[vb_off(r1, c0 + 1)] = __float2half_rn(acc[nb][1]);
                Ps[vb_off(r2, c0)]     = __float2half_rn(acc[nb][2]);
                Ps[vb_off(r2, c0 + 1)] = __float2half_rn(acc[nb][3]);
            } else if (p == 1) {
                *(unsigned*)(Ps + kb_off(r1, c0)) = pack2(acc[nb][0], acc[nb][1]);
                *(unsigned*)(Ps + kb_off(r2, c0)) = pack2(acc[nb][2], acc[nb][3]);
            } else {
                *(unsigned*)(Ps + qa_off(r1, c0)) =
                    pack2(acc[nb][0] * QSCALE, acc[nb][1] * QSCALE);
                *(unsigned*)(Ps + qa_off(r2, c0)) =
                    pack2(acc[nb][2] * QSCALE, acc[nb][3] * QSCALE);
            }
        }
        __syncthreads();

        const size_t hb = (size_t)(n * NHEADS + h) * L_SEQ * HDIM;
        __half* dst;
        if (p == 0)      dst = g_v + hb + (size_t)lt * 4096;
        else if (p == 1) dst = g_k + hb + (size_t)lt * 4096;
        else             dst = g_q + hb + (size_t)(l0 >> 7) * 8192 + ((l0 & 64) ? 4096 : 0);
        for (int i = tid; i < 512; i += 256)
            ((uint4*)dst)[i] = ((const uint4*)Ps)[i];
        __syncthreads();
    }
}

// ---------------- kernel 2: fp16 flash attention (2 warps x 32 rows) ----------
// smem bytes: KB[3] 8192 each | VB[3] 8192 each = 49152
#define OFF_KB  0
#define OFF_VB  24576
#define ATTN_SMEM 49152

__global__ __launch_bounds__(64, 4) void attn_kernel(float* __restrict__ out)
{
    extern __shared__ char smc[];
    const int qt = blockIdx.x;            // 64-row tile index (0..31)
    const int h = blockIdx.y, n = blockIdx.z;
    const int qt128 = qt >> 1;
    const int tid = threadIdx.x, warp = tid >> 5, lane = tid & 31;
    const int grp = lane >> 2, t = lane & 3;
    const int bg0 = (qt & 1) * 4 + 2 * warp;   // first 16-row block id in qt128

    const __half* qg = g_q + ((size_t)(n * NHEADS + h) * 16 + qt128) * 8192;
    const __half* kg = g_k + (size_t)(n * NHEADS + h) * L_SEQ * HDIM;
    const __half* vg = g_v + (size_t)(n * NHEADS + h) * L_SEQ * HDIM;
    // mask fragments for this warp's two 16-row blocks (bg0, bg0+1)
    const uint4* mf0 = g_mf + ((size_t)(n * 16 + qt128) * 32 * 256 + bg0 * 32 + lane) * 4;
    const uint4* mf1 = mf0 + 32 * 4;

    const uint32_t sb = (uint32_t)__cvta_generic_to_shared(smc);

    // prologue: G0 = {K0, V0}; G1 = {K1, V1}   (64 threads x 8 uint4 = 512)
    #pragma unroll
    for (int j = 0; j < 8; ++j) {
        cpa16(sb + OFF_KB + (tid + j * 64) * 16, (const uint4*)kg + tid + j * 64);
        cpa16(sb + OFF_VB + (tid + j * 64) * 16, (const uint4*)vg + tid + j * 64);
    }
    CP_COMMIT();
    #pragma unroll
    for (int j = 0; j < 8; ++j) {
        cpa16(sb + OFF_KB + 8192 + (tid + j * 64) * 16, (const uint4*)(kg + 4096) + tid + j * 64);
        cpa16(sb + OFF_VB + 8192 + (tid + j * 64) * 16, (const uint4*)(vg + 4096) + tid + j * 64);
    }
    CP_COMMIT();

    // Q fragments for both row blocks (fragment-ordered gmem, one LDG pass)
    unsigned qa[2][4][4];
    #pragma unroll
    for (int b = 0; b < 2; ++b) {
        const uint4* qg4 = (const uint4*)qg + (bg0 + b) * 128 + lane;
        #pragma unroll
        for (int kk = 0; kk < 4; ++kk) {
            uint4 v = qg4[kk * 32];
            qa[b][kk][0] = v.x; qa[b][kk][1] = v.y; qa[b][kk][2] = v.z; qa[b][kk][3] = v.w;
        }
    }

    float o[2][8][4];
    #pragma unroll
    for (int b = 0; b < 2; ++b)
        #pragma unroll
        for (int j = 0; j < 8; ++j)
            o[b][j][0] = o[b][j][1] = o[b][j][2] = o[b][j][3] = 0.f;
    float ld[2][4] = {};

    int cur = 0, nxt = 2;
    for (int kti = 0; kti < NT; ++kti) {
        uint4 mk0[4], mk1[4];
        #pragma unroll
        for (int kk = 0; kk < 4; ++kk) {
            mk0[kk] = mf0[(size_t)kti * 1024 + kk];
            mk1[kk] = mf1[(size_t)kti * 1024 + kk];
        }

        CP_WAIT(1);
        __syncthreads();

        if (kti + 2 < NT) {
            const uint4* k2 = (const uint4*)(kg + (size_t)(kti + 2) * 4096);
            const uint4* v2 = (const uint4*)(vg + (size_t)(kti + 2) * 4096);
            const uint32_t kd = sb + OFF_KB + nxt * 8192;
            const uint32_t vd = sb + OFF_VB + nxt * 8192;
            #pragma unroll
            for (int j = 0; j < 8; ++j) {
                cpa16(kd + (tid + j * 64) * 16, k2 + tid + j * 64);
                cpa16(vd + (tid + j * 64) * 16, v2 + tid + j * 64);
            }
        }
        CP_COMMIT();

        const uint4* kb4 = (const uint4*)(smc + OFF_KB + cur * 8192) + lane;
        const uint4* vb4 = (const uint4*)(smc + OFF_VB + cur * 8192) + lane;

        // ---- S = Q K^T, fp16 accumulators (fully fused tensor block) ----
        unsigned su[2][16];
        #pragma unroll
        for (int kk = 0; kk < 4; ++kk) {
            #pragma unroll
            for (int jp = 0; jp < 4; ++jp) {
                uint4 bv = kb4[kk * 128 + jp * 32];
                if (kk == 0) {
                    #pragma unroll
                    for (int b = 0; b < 2; ++b) {
                        mma16h_z(su[b][4 * jp],     su[b][4 * jp + 1], qa[b][0], bv.x, bv.y);
                        mma16h_z(su[b][4 * jp + 2], su[b][4 * jp + 3], qa[b][0], bv.z, bv.w);
                    }
                } else {
                    #pragma unroll
                    for (int b = 0; b < 2; ++b) {
                        mma16h(su[b][4 * jp],     su[b][4 * jp + 1], qa[b][kk], bv.x, bv.y);
                        mma16h(su[b][4 * jp + 2], su[b][4 * jp + 3], qa[b][kk], bv.z, bv.w);
                    }
                }
            }
        }

        // ---- per 16-wide P group g: JIT ex2+mask, then that group's PV ----
        // (MUFU work is spread between mma blocks so co-resident warps can
        //  keep the tensor pipe busy during this warp's ex2 slices)
        #pragma unroll
        for (int g = 0; g < 4; ++g) {
            ex2h2(su[0][4 * g]);     ex2h2(su[0][4 * g + 1]);
            ex2h2(su[0][4 * g + 2]); ex2h2(su[0][4 * g + 3]);
            ex2h2(su[1][4 * g]);     ex2h2(su[1][4 * g + 1]);
            ex2h2(su[1][4 * g + 2]); ex2h2(su[1][4 * g + 3]);
            su[0][4 * g]     &= mk0[g].x; su[0][4 * g + 1] &= mk0[g].y;
            su[0][4 * g + 2] &= mk0[g].z; su[0][4 * g + 3] &= mk0[g].w;
            su[1][4 * g]     &= mk1[g].x; su[1][4 * g + 1] &= mk1[g].y;
            su[1][4 * g + 2] &= mk1[g].z; su[1][4 * g + 3] &= mk1[g].w;

            #pragma unroll
            for (int jp = 0; jp < 4; ++jp) {
                uint4 bv = vb4[g * 128 + jp * 32];
                #pragma unroll
                for (int b = 0; b < 2; ++b) {
                    mma16(o[b][jp * 2],     su[b] + 4 * g, bv.x, bv.y);
                    mma16(o[b][jp * 2 + 1], su[b] + 4 * g, bv.z, bv.w);
                }
            }
            mma16(ld[0], su[0] + 4 * g, ONES2, ONES2);
            mma16(ld[1], su[1] + 4 * g, ONES2, ONES2);
        }

        cur = (cur == 2) ? 0 : cur + 1;
        nxt = (nxt == 2) ? 0 : nxt + 1;
    }

    // ---- epilogue per row block ----
    const int q0 = qt128 * 128;
    #pragma unroll
    for (int b = 0; b < 2; ++b) {
        const int ra = (bg0 + b) * 16 + grp;
        const float inv1 = 1.f / ld[b][0], inv2 = 1.f / ld[b][2];
        float* ob1 = out + ((size_t)(n * L_SEQ + q0 + ra)) * EMBED + h * HDIM;
        float* ob2 = out + ((size_t)(n * L_SEQ + q0 + ra + 8)) * EMBED + h * HDIM;
        #pragma unroll
        for (int j = 0; j < 8; ++j) {
            int c0 = j * 8 + 2 * t;
            *(float2*)(ob1 + c0) = make_float2(o[b][j][0] * inv1, o[b][j][1] * inv1);
            *(float2*)(ob2 + c0) = make_float2(o[b][j][2] * inv2, o[b][j][3] * inv2);
        }
    }
}

// ---------------- launch ------------------------------------------------------
extern "C" void kernel_launch(void* const* d_in, const int* in_sizes, int n_in,
                              void* d_out, int out_size)
{
    const float* values  = (const float*)d_in[0];
    const float* keys    = (const float*)d_in[1];
    const float* queries = (const float*)d_in[2];
    const int*   mask    = (const int*)d_in[3];
    const float* Wv      = (const float*)d_in[4];
    const float* Wk      = (const float*)d_in[5];
    const float* Wq      = (const float*)d_in[6];
    float* out = (float*)d_out;

    cudaFuncSetAttribute(attn_kernel, cudaFuncAttributeMaxDynamicSharedMemorySize, ATTN_SMEM);

    proj_kernel<<<dim3(L_SEQ / 64, NHEADS, NBATCH), 256>>>(
        values, keys, queries, Wv, Wk, Wq, mask);
    attn_kernel<<<dim3(L_SEQ / 64, NHEADS, NBATCH), 64, ATTN_SMEM>>>(out);
}